// round 11
// baseline (speedup 1.0000x reference)
#include <cuda_runtime.h>
#include <cuda_bf16.h>
#include <cstdint>

#define B_ 16
#define C_ 32
#define V_ 512
#define L_ 168
#define VL_ (V_*L_)                      // 86016
#define CVL_ (C_*VL_)                    // 2752512
#define NELEM ((size_t)B_*C_*V_*L_)      // 44040192
#define ALPHA 0.05f
#define OMA   0.95f

// ---------------- device scratch ----------------
__device__ float g_d[V_];
__device__ __nv_bfloat16 g_Phi[V_*V_];
__device__ __nv_bfloat16 g_Plo[V_*V_];
__device__ __nv_bfloat16 g_xhi[NELEM];
__device__ __nv_bfloat16 g_xlo[NELEM];
__device__ __nv_bfloat16 g_hhi[3*NELEM];
__device__ __nv_bfloat16 g_hlo[3*NELEM];

// ---------------- PTX helpers ----------------
__device__ __forceinline__ void cpasync16(uint32_t dst, const void* src) {
    asm volatile("cp.async.cg.shared.global [%0],[%1],16;\n" :: "r"(dst), "l"(src));
}
__device__ __forceinline__ void cpcommit() { asm volatile("cp.async.commit_group;\n"); }
template<int N> __device__ __forceinline__ void cpwait() {
    asm volatile("cp.async.wait_group %0;\n" :: "n"(N));
}
__device__ __forceinline__ void bar_sync(int id, int cnt) {
    asm volatile("bar.sync %0, %1;" :: "r"(id), "r"(cnt) : "memory");
}
__device__ __forceinline__ void bar_arrive(int id, int cnt) {
    asm volatile("bar.arrive %0, %1;" :: "r"(id), "r"(cnt) : "memory");
}
__device__ __forceinline__ void ldsm_x4(uint32_t a[4], uint32_t addr) {
    asm volatile("ldmatrix.sync.aligned.m8n8.x4.shared.b16 {%0,%1,%2,%3},[%4];"
        : "=r"(a[0]), "=r"(a[1]), "=r"(a[2]), "=r"(a[3]) : "r"(addr));
}
__device__ __forceinline__ void ldsm_x4t(uint32_t a[4], uint32_t addr) {
    asm volatile("ldmatrix.sync.aligned.m8n8.x4.trans.shared.b16 {%0,%1,%2,%3},[%4];"
        : "=r"(a[0]), "=r"(a[1]), "=r"(a[2]), "=r"(a[3]) : "r"(addr));
}
__device__ __forceinline__ void ldsm_x2t(uint32_t b[2], uint32_t addr) {
    asm volatile("ldmatrix.sync.aligned.m8n8.x2.trans.shared.b16 {%0,%1},[%2];"
        : "=r"(b[0]), "=r"(b[1]) : "r"(addr));
}
__device__ __forceinline__ void mma16816(float c[4], const uint32_t a[4], const uint32_t b[2]) {
    asm volatile("mma.sync.aligned.m16n8k16.row.col.f32.bf16.bf16.f32 "
        "{%0,%1,%2,%3},{%4,%5,%6,%7},{%8,%9},{%0,%1,%2,%3};"
        : "+f"(c[0]), "+f"(c[1]), "+f"(c[2]), "+f"(c[3])
        : "r"(a[0]), "r"(a[1]), "r"(a[2]), "r"(a[3]), "r"(b[0]), "r"(b[1]));
}

// ---------------- adjacency prep ----------------
__global__ void rowsum_kernel(const float* __restrict__ adj) {
    int v = blockIdx.x;
    float s = 0.f;
    for (int w = threadIdx.x; w < V_; w += blockDim.x) s += adj[v*V_ + w];
    __shared__ float sh[128];
    sh[threadIdx.x] = s;
    __syncthreads();
    for (int off = 64; off > 0; off >>= 1) {
        if (threadIdx.x < off) sh[threadIdx.x] += sh[threadIdx.x + off];
        __syncthreads();
    }
    if (threadIdx.x == 0) g_d[v] = sh[0] + 1.0f;
}

__global__ void buildP_kernel(const float* __restrict__ adj) {
    int idx = blockIdx.x * blockDim.x + threadIdx.x;   // idx = w*512 + v
    int w = idx >> 9, v = idx & 511;
    float a = adj[v*V_ + w] + (v == w ? 1.f : 0.f);
    float p = a / g_d[v];
    __nv_bfloat16 hi = __float2bfloat16_rn(p);
    g_Phi[idx] = hi;
    g_Plo[idx] = __float2bfloat16_rn(p - __bfloat162float(hi));
}

__global__ void split_kernel(const float* __restrict__ x) {
    size_t i = ((size_t)blockIdx.x * 256 + threadIdx.x) * 4;
    float4 v = *(const float4*)(x + i);
    __nv_bfloat16 h0 = __float2bfloat16_rn(v.x), h1 = __float2bfloat16_rn(v.y);
    __nv_bfloat16 h2 = __float2bfloat16_rn(v.z), h3 = __float2bfloat16_rn(v.w);
    *(__nv_bfloat162*)(g_xhi + i)     = __halves2bfloat162(h0, h1);
    *(__nv_bfloat162*)(g_xhi + i + 2) = __halves2bfloat162(h2, h3);
    *(__nv_bfloat162*)(g_xlo + i)     = __halves2bfloat162(
        __float2bfloat16_rn(v.x - __bfloat162float(h0)),
        __float2bfloat16_rn(v.y - __bfloat162float(h1)));
    *(__nv_bfloat162*)(g_xlo + i + 2) = __halves2bfloat162(
        __float2bfloat16_rn(v.z - __bfloat162float(h2)),
        __float2bfloat16_rn(v.w - __bfloat162float(h3)));
}

// ---------------- tensor-core propagation (warp-specialized) ----------------
// Tile BM=64 x BN=168, BK=32; 256 threads: warps 0-5 consumers (2m x 3n,
// warp tile 32x56), warps 6-7 producers (all cp.async). 2 CTAs/SM.
// 3-slot smem ring; handoff via named barriers full[i]=1+i / free[i]=4+i.
#define A_ST   80
#define A_TERM 5120    // 64*80
#define B_OFF  10240   // 2*A_TERM
#define B_ROW  336     // 168 bf16
#define B_TERM 10752   // 32*336
#define STAGE  31744   // B_OFF + 2*B_TERM
#define NSTG   3
#define PROP_SMEM (NSTG*STAGE)   // 95232
#define NKK    32
#define BARCNT 256

__global__ __launch_bounds__(256, 2) void prop_mma(const float* __restrict__ xg,
                                                   int src_sel, int dst_sel) {
    extern __shared__ char smem[];
    uint32_t sb = (uint32_t)__cvta_generic_to_shared(smem);
    const int t = threadIdx.x;
    const int warp = t >> 5, lane = t & 31;
    const int w0 = blockIdx.x * 64;
    const int bc0 = blockIdx.y * 2;

    const __nv_bfloat16* __restrict__ shi =
        (src_sel < 0) ? g_xhi : (g_hhi + (size_t)src_sel * NELEM);
    const __nv_bfloat16* __restrict__ slo =
        (src_sel < 0) ? g_xlo : (g_hlo + (size_t)src_sel * NELEM);
    __nv_bfloat16* __restrict__ dhi = g_hhi + (size_t)dst_sel * NELEM;
    __nv_bfloat16* __restrict__ dlo = g_hlo + (size_t)dst_sel * NELEM;

    if (warp >= 6) {
        // ---------------- producer: 64 threads own all loads ----------------
        const int pt = t - 192;           // 0..63
        auto issue = [&](int slot, int kk) {
            const int g = kk >> 4, kt = kk & 15;
            const size_t base = (size_t)(bc0 + g) * VL_;
            const uint32_t st = sb + slot * STAGE;
            #pragma unroll
            for (int i = 0; i < 8; i++) {             // A: 512 chunks
                int c = i * 64 + pt;
                int term = c >> 8, rem = c & 255;
                int row = rem >> 2, q = rem & 3;
                const __nv_bfloat16* src = (term ? g_Plo : g_Phi)
                    + (size_t)(w0 + row) * V_ + kt * 32 + q * 8;
                cpasync16(st + term * A_TERM + row * A_ST + q * 16, src);
            }
            #pragma unroll
            for (int i = 0; i < 21; i++) {            // B: 1344 chunks
                int c = i * 64 + pt;
                int term = c / 672, rem = c - term * 672;
                int row = rem / 21, cc = rem - row * 21;
                const __nv_bfloat16* src = (term ? slo : shi) + base
                    + (size_t)(kt * 32 + row) * L_ + cc * 8;
                cpasync16(st + B_OFF + term * B_TERM + row * B_ROW + cc * 16, src);
            }
            cpcommit();
        };
        for (int s = 0; s < NKK; s++) {
            if (s >= NSTG) bar_sync(4 + s % NSTG, BARCNT);     // slot free?
            issue(s % NSTG, s);
            if (s >= 2) { cpwait<2>(); bar_arrive(1 + (s - 2) % NSTG, BARCNT); }
        }
        cpwait<1>(); bar_arrive(1 + (NKK - 2) % NSTG, BARCNT);
        cpwait<0>(); bar_arrive(1 + (NKK - 1) % NSTG, BARCNT);
        return;
    }

    // ---------------- consumer: 6 warps, pure LDSM + MMA ----------------
    const int warp_m = warp & 1, warp_n = warp >> 1;     // 2 x 3

    float acc[2][7][4];
    #pragma unroll
    for (int i = 0; i < 2; i++)
        #pragma unroll
        for (int j = 0; j < 7; j++)
            #pragma unroll
            for (int q = 0; q < 4; q++) acc[i][j][q] = 0.f;

    for (int kk = 0; kk < NKK; kk++) {
        bar_sync(1 + kk % NSTG, BARCNT);                 // slot full?
        const uint32_t st = sb + (kk % NSTG) * STAGE;
        #pragma unroll
        for (int ks = 0; ks < 2; ks++) {
            const uint32_t browb = st + B_OFF
                + (ks * 16 + (lane & 15)) * B_ROW + warp_n * 112
                + (lane >> 4) * 16;

            uint32_t bh[7][2];
            #pragma unroll
            for (int jp = 0; jp < 3; jp++) {
                uint32_t tmp[4];
                ldsm_x4t(tmp, browb + (2 * jp) * 16);
                bh[2*jp][0] = tmp[0]; bh[2*jp][1] = tmp[1];
                bh[2*jp+1][0] = tmp[2]; bh[2*jp+1][1] = tmp[3];
            }
            ldsm_x2t(bh[6], browb + 6 * 16);

            uint32_t ah[2][4], al[2][4];
            #pragma unroll
            for (int i = 0; i < 2; i++) {
                int rowA = warp_m * 32 + i * 16 + (lane & 15);
                uint32_t off = rowA * A_ST + ks * 32 + (lane >> 4) * 16;
                ldsm_x4(ah[i], st + off);
                ldsm_x4(al[i], st + A_TERM + off);
            }

            #pragma unroll
            for (int j = 0; j < 7; j++)
                #pragma unroll
                for (int i = 0; i < 2; i++)
                    mma16816(acc[i][j], ah[i], bh[j]);
            #pragma unroll
            for (int j = 0; j < 7; j++)
                #pragma unroll
                for (int i = 0; i < 2; i++)
                    mma16816(acc[i][j], al[i], bh[j]);

            uint32_t bl[7][2];
            #pragma unroll
            for (int jp = 0; jp < 3; jp++) {
                uint32_t tmp[4];
                ldsm_x4t(tmp, browb + B_TERM + (2 * jp) * 16);
                bl[2*jp][0] = tmp[0]; bl[2*jp][1] = tmp[1];
                bl[2*jp+1][0] = tmp[2]; bl[2*jp+1][1] = tmp[3];
            }
            ldsm_x2t(bl[6], browb + B_TERM + 6 * 16);
            #pragma unroll
            for (int j = 0; j < 7; j++)
                #pragma unroll
                for (int i = 0; i < 2; i++)
                    mma16816(acc[i][j], ah[i], bl[j]);
        }
        bar_arrive(4 + kk % NSTG, BARCNT);               // slot free

        if ((kk & 15) == 15) {
            // epilogue for bc = bc0 + (kk>>4); producer keeps loading meanwhile
            const size_t base = (size_t)(bc0 + (kk >> 4)) * VL_;
            const int gr = lane >> 2, gc = (lane & 3) * 2;
            #pragma unroll
            for (int i = 0; i < 2; i++) {
                #pragma unroll
                for (int j = 0; j < 7; j++) {
                    #pragma unroll
                    for (int h = 0; h < 2; h++) {
                        int wrow = w0 + warp_m * 32 + i * 16 + gr + h * 8;
                        int lcol = warp_n * 56 + j * 8 + gc;
                        size_t off = base + (size_t)wrow * L_ + lcol;
                        float2 xv = *(const float2*)(xg + off);
                        float o0 = ALPHA * xv.x + OMA * acc[i][j][2*h + 0];
                        float o1 = ALPHA * xv.y + OMA * acc[i][j][2*h + 1];
                        __nv_bfloat16 b0 = __float2bfloat16_rn(o0);
                        __nv_bfloat16 b1 = __float2bfloat16_rn(o1);
                        *(__nv_bfloat162*)(dhi + off) = __halves2bfloat162(b0, b1);
                        *(__nv_bfloat162*)(dlo + off) = __halves2bfloat162(
                            __float2bfloat16_rn(o0 - __bfloat162float(b0)),
                            __float2bfloat16_rn(o1 - __bfloat162float(b1)));
                        acc[i][j][2*h + 0] = 0.f;
                        acc[i][j][2*h + 1] = 0.f;
                    }
                }
            }
        }
    }
}

// ---------------- tensor-core channel mix ----------------
#define MROW 272      // padded row stride bytes (128 bf16 = 256B + 16 pad)
#define MTERM 8704    // 32*272
#define WBYTES 17408  // 2 terms of W
#define MSTAGE 17408  // 2 terms of B
#define MIX_SMEM (WBYTES + 2*MSTAGE)   // 52224

__global__ __launch_bounds__(128) void mix_mma(const float* __restrict__ Wg,
                                               const float* __restrict__ bias,
                                               float* __restrict__ out) {
    extern __shared__ char smem[];
    uint32_t sb = (uint32_t)__cvta_generic_to_shared(smem);
    const int t = threadIdx.x;
    const int warp = t >> 5, lane = t & 31;
    const int n0 = blockIdx.x * 128;       // position within (v,l) plane
    const int b = blockIdx.y;
    const size_t boff = (size_t)b * CVL_;

    #pragma unroll
    for (int i = 0; i < 32; i++) {
        int idx = i * 128 + t;             // 4096 total
        int o = idx >> 7, ch = idx & 127;
        float w = Wg[idx];
        __nv_bfloat16 hi = __float2bfloat16_rn(w);
        __nv_bfloat16 lo = __float2bfloat16_rn(w - __bfloat162float(hi));
        *(__nv_bfloat16*)(smem + o * MROW + ch * 2) = hi;
        *(__nv_bfloat16*)(smem + MTERM + o * MROW + ch * 2) = lo;
    }

    const __nv_bfloat16* hitbl[4] = { g_xhi + boff, g_hhi + boff,
                                      g_hhi + NELEM + boff, g_hhi + 2*NELEM + boff };
    const __nv_bfloat16* lotbl[4] = { g_xlo + boff, g_hlo + boff,
                                      g_hlo + NELEM + boff, g_hlo + 2*NELEM + boff };

    auto issue = [&](int s, int kt) {
        uint32_t st = sb + WBYTES + s * MSTAGE;
        #pragma unroll
        for (int i = 0; i < 8; i++) {                  // 1024 chunks exactly
            int c = i * 128 + t;
            int term = c >> 9, rem = c & 511;
            int row = rem >> 4, cc = rem & 15;
            const __nv_bfloat16* src = (term ? lotbl[kt] : hitbl[kt])
                + (size_t)row * VL_ + n0 + cc * 8;
            cpasync16(st + term * MTERM + row * MROW + cc * 16, src);
        }
        cpcommit();
    };

    float acc[2][4][4];
    #pragma unroll
    for (int i = 0; i < 2; i++)
        #pragma unroll
        for (int j = 0; j < 4; j++)
            #pragma unroll
            for (int q = 0; q < 4; q++) acc[i][j][q] = 0.f;

    issue(0, 0);
    for (int kt = 0; kt < 4; kt++) {
        if (kt < 3) { issue((kt + 1) & 1, kt + 1); cpwait<1>(); }
        else        { cpwait<0>(); }
        __syncthreads();
        uint32_t st = sb + WBYTES + (kt & 1) * MSTAGE;
        #pragma unroll
        for (int ks = 0; ks < 2; ks++) {
            int kchunk = kt * 2 + ks;
            uint32_t awh[2][4], awl[2][4];
            #pragma unroll
            for (int i = 0; i < 2; i++) {
                int rowA = i * 16 + (lane & 15);
                uint32_t aoff = rowA * MROW + kchunk * 32 + (lane >> 4) * 16;
                ldsm_x4(awh[i], sb + aoff);
                ldsm_x4(awl[i], sb + MTERM + aoff);
            }
            int rowB = ks * 16 + (lane & 15);
            uint32_t bh[4][2], bl[4][2];
            #pragma unroll
            for (int j = 0; j < 4; j++) {
                uint32_t bo = st + rowB * MROW + warp * 64 + j * 16;
                ldsm_x2t(bh[j], bo);
                ldsm_x2t(bl[j], bo + MTERM);
            }
            #pragma unroll
            for (int j = 0; j < 4; j++)
                #pragma unroll
                for (int i = 0; i < 2; i++)
                    mma16816(acc[i][j], awh[i], bh[j]);
            #pragma unroll
            for (int j = 0; j < 4; j++)
                #pragma unroll
                for (int i = 0; i < 2; i++)
                    mma16816(acc[i][j], awh[i], bl[j]);
            #pragma unroll
            for (int j = 0; j < 4; j++)
                #pragma unroll
                for (int i = 0; i < 2; i++)
                    mma16816(acc[i][j], awl[i], bh[j]);
        }
        __syncthreads();
    }

    const int gr = lane >> 2, gc = (lane & 3) * 2;
    #pragma unroll
    for (int i = 0; i < 2; i++) {
        int o0 = i * 16 + gr;
        float bv0 = __ldg(bias + o0);
        float bv1 = __ldg(bias + o0 + 8);
        #pragma unroll
        for (int j = 0; j < 4; j++) {
            int p = n0 + warp * 32 + j * 8 + gc;
            *(float2*)(out + boff + (size_t)o0 * VL_ + p) =
                make_float2(acc[i][j][0] + bv0, acc[i][j][1] + bv0);
            *(float2*)(out + boff + (size_t)(o0 + 8) * VL_ + p) =
                make_float2(acc[i][j][2] + bv1, acc[i][j][3] + bv1);
        }
    }
}

extern "C" void kernel_launch(void* const* d_in, const int* in_sizes, int n_in,
                              void* d_out, int out_size) {
    (void)in_sizes; (void)n_in; (void)out_size;
    const float* x    = (const float*)d_in[0];
    const float* adj  = (const float*)d_in[1];
    const float* W    = (const float*)d_in[2];
    const float* bias = (const float*)d_in[3];
    float* out = (float*)d_out;

    cudaFuncSetAttribute(prop_mma, cudaFuncAttributeMaxDynamicSharedMemorySize,
                         PROP_SMEM);
    cudaFuncSetAttribute(mix_mma, cudaFuncAttributeMaxDynamicSharedMemorySize,
                         MIX_SMEM);

    rowsum_kernel<<<V_, 128>>>(adj);
    buildP_kernel<<<(V_*V_)/256, 256>>>(adj);
    split_kernel<<<(int)(NELEM/4/256), 256>>>(x);

    dim3 pgrid(V_/64, (B_*C_)/2);    // (8, 256) = 2048 CTAs, 2/SM
    prop_mma<<<pgrid, 256, PROP_SMEM>>>(x, -1, 0);   // h1 = f(x)
    prop_mma<<<pgrid, 256, PROP_SMEM>>>(x,  0, 1);   // h2 = f(h1)
    prop_mma<<<pgrid, 256, PROP_SMEM>>>(x,  1, 2);   // h3 = f(h2)

    mix_mma<<<dim3(VL_/128, B_), 128, MIX_SMEM>>>(W, bias, out);
}

// round 13
// speedup vs baseline: 1.0305x; 1.0305x over previous
#include <cuda_runtime.h>
#include <cuda_bf16.h>
#include <cstdint>

#define B_ 16
#define C_ 32
#define V_ 512
#define L_ 168
#define VL_ (V_*L_)                      // 86016
#define CVL_ (C_*VL_)                    // 2752512
#define NELEM ((size_t)B_*C_*V_*L_)      // 44040192
#define ALPHA 0.05f
#define OMA   0.95f

// ---------------- device scratch ----------------
__device__ float g_d[V_];
__device__ __nv_bfloat16 g_Phi[V_*V_];
__device__ __nv_bfloat16 g_Plo[V_*V_];
__device__ __nv_bfloat16 g_xhi[NELEM];
__device__ __nv_bfloat16 g_xlo[NELEM];
__device__ __nv_bfloat16 g_hhi[3*NELEM];
__device__ __nv_bfloat16 g_hlo[3*NELEM];

// ---------------- PTX helpers ----------------
__device__ __forceinline__ void cpasync16(uint32_t dst, const void* src) {
    asm volatile("cp.async.cg.shared.global [%0],[%1],16;\n" :: "r"(dst), "l"(src));
}
__device__ __forceinline__ void cpcommit() { asm volatile("cp.async.commit_group;\n"); }
template<int N> __device__ __forceinline__ void cpwait() {
    asm volatile("cp.async.wait_group %0;\n" :: "n"(N));
}
__device__ __forceinline__ void ldsm_x4(uint32_t a[4], uint32_t addr) {
    asm volatile("ldmatrix.sync.aligned.m8n8.x4.shared.b16 {%0,%1,%2,%3},[%4];"
        : "=r"(a[0]), "=r"(a[1]), "=r"(a[2]), "=r"(a[3]) : "r"(addr));
}
__device__ __forceinline__ void ldsm_x4t(uint32_t a[4], uint32_t addr) {
    asm volatile("ldmatrix.sync.aligned.m8n8.x4.trans.shared.b16 {%0,%1,%2,%3},[%4];"
        : "=r"(a[0]), "=r"(a[1]), "=r"(a[2]), "=r"(a[3]) : "r"(addr));
}
__device__ __forceinline__ void ldsm_x2t(uint32_t b[2], uint32_t addr) {
    asm volatile("ldmatrix.sync.aligned.m8n8.x2.trans.shared.b16 {%0,%1},[%2];"
        : "=r"(b[0]), "=r"(b[1]) : "r"(addr));
}
__device__ __forceinline__ void mma16816(float c[4], const uint32_t a[4], const uint32_t b[2]) {
    asm volatile("mma.sync.aligned.m16n8k16.row.col.f32.bf16.bf16.f32 "
        "{%0,%1,%2,%3},{%4,%5,%6,%7},{%8,%9},{%0,%1,%2,%3};"
        : "+f"(c[0]), "+f"(c[1]), "+f"(c[2]), "+f"(c[3])
        : "r"(a[0]), "r"(a[1]), "r"(a[2]), "r"(a[3]), "r"(b[0]), "r"(b[1]));
}

// ---------------- adjacency prep ----------------
__global__ void rowsum_kernel(const float* __restrict__ adj) {
    int v = blockIdx.x;
    float s = 0.f;
    for (int w = threadIdx.x; w < V_; w += blockDim.x) s += adj[v*V_ + w];
    __shared__ float sh[128];
    sh[threadIdx.x] = s;
    __syncthreads();
    for (int off = 64; off > 0; off >>= 1) {
        if (threadIdx.x < off) sh[threadIdx.x] += sh[threadIdx.x + off];
        __syncthreads();
    }
    if (threadIdx.x == 0) g_d[v] = sh[0] + 1.0f;
}

__global__ void buildP_kernel(const float* __restrict__ adj) {
    int idx = blockIdx.x * blockDim.x + threadIdx.x;   // idx = w*512 + v
    int w = idx >> 9, v = idx & 511;
    float a = adj[v*V_ + w] + (v == w ? 1.f : 0.f);
    float p = a / g_d[v];
    __nv_bfloat16 hi = __float2bfloat16_rn(p);
    g_Phi[idx] = hi;
    g_Plo[idx] = __float2bfloat16_rn(p - __bfloat162float(hi));
}

__global__ void split_kernel(const float* __restrict__ x) {
    size_t i = ((size_t)blockIdx.x * 256 + threadIdx.x) * 4;
    float4 v = *(const float4*)(x + i);
    __nv_bfloat16 h0 = __float2bfloat16_rn(v.x), h1 = __float2bfloat16_rn(v.y);
    __nv_bfloat16 h2 = __float2bfloat16_rn(v.z), h3 = __float2bfloat16_rn(v.w);
    *(__nv_bfloat162*)(g_xhi + i)     = __halves2bfloat162(h0, h1);
    *(__nv_bfloat162*)(g_xhi + i + 2) = __halves2bfloat162(h2, h3);
    *(__nv_bfloat162*)(g_xlo + i)     = __halves2bfloat162(
        __float2bfloat16_rn(v.x - __bfloat162float(h0)),
        __float2bfloat16_rn(v.y - __bfloat162float(h1)));
    *(__nv_bfloat162*)(g_xlo + i + 2) = __halves2bfloat162(
        __float2bfloat16_rn(v.z - __bfloat162float(h2)),
        __float2bfloat16_rn(v.w - __bfloat162float(h3)));
}

// ---------------- tensor-core propagation ----------------
// Tile BM=64 x BN=168, BK=32; 192 threads = 6 warps (2m x 3n), warp 32x56.
// 2 CTAs/SM. Each stage holds A(kt) ONCE + B(kt,bc0) + B(kt,bc1); both bc
// accumulate simultaneously -> 19% fewer load ops, half the syncs vs R9.
// Outer kt loop kept rolled (#pragma unroll 1) to bound code size.
#define A_ST   80
#define A_TERM 5120    // hi: 64 rows x 80B; lo at +5120
#define B_OFF  10240   // 2*A_TERM
#define B_ROW  336     // 168 bf16
#define B_TERM 10752   // 32*336
#define B_GRP  21504   // 2 terms per bc group
#define STAGE  53248   // B_OFF + 2*B_GRP
#define PROP_SMEM (2*STAGE)   // 106496 per CTA

__global__ __launch_bounds__(192, 2) void prop_mma(const float* __restrict__ xg,
                                                   int src_sel, int dst_sel) {
    extern __shared__ char smem[];
    uint32_t sb = (uint32_t)__cvta_generic_to_shared(smem);
    const int t = threadIdx.x;
    const int warp = t >> 5, lane = t & 31;
    const int warp_m = warp & 1, warp_n = warp >> 1;     // 2 x 3
    const int w0 = blockIdx.x * 64;
    const int bc0 = blockIdx.y * 2;

    const __nv_bfloat16* __restrict__ shi =
        (src_sel < 0) ? g_xhi : (g_hhi + (size_t)src_sel * NELEM);
    const __nv_bfloat16* __restrict__ slo =
        (src_sel < 0) ? g_xlo : (g_hlo + (size_t)src_sel * NELEM);
    __nv_bfloat16* __restrict__ dhi = g_hhi + (size_t)dst_sel * NELEM;
    __nv_bfloat16* __restrict__ dlo = g_hlo + (size_t)dst_sel * NELEM;

    // one stage = A(kt) + B(kt, bc0) + B(kt, bc1): 3200 16B chunks
    auto issue = [&](int slot, int kt) {
        const uint32_t st = sb + slot * STAGE;
        #pragma unroll
        for (int i = 0; i < 17; i++) {
            int c = i * 192 + t;
            if (c < 512) {                            // A
                int term = c >> 8, rem = c & 255;
                int row = rem >> 2, q = rem & 3;
                const __nv_bfloat16* src = (term ? g_Plo : g_Phi)
                    + (size_t)(w0 + row) * V_ + kt * 32 + q * 8;
                cpasync16(st + term * A_TERM + row * A_ST + q * 16, src);
            } else if (c < 3200) {                    // B, both bc groups
                int b = c - 512;
                int g = b / 1344, rem = b - g * 1344;
                int term = rem / 672, r2 = rem - term * 672;
                int row = r2 / 21, cc = r2 - row * 21;
                const __nv_bfloat16* src = (term ? slo : shi)
                    + (size_t)(bc0 + g) * VL_
                    + (size_t)(kt * 32 + row) * L_ + cc * 8;
                cpasync16(st + B_OFF + g * B_GRP + term * B_TERM
                          + row * B_ROW + cc * 16, src);
            }
        }
        cpcommit();
    };

    float acc[2][2][7][4];   // [g][i][j][q]
    #pragma unroll
    for (int g = 0; g < 2; g++)
        #pragma unroll
        for (int i = 0; i < 2; i++)
            #pragma unroll
            for (int j = 0; j < 7; j++)
                #pragma unroll
                for (int q = 0; q < 4; q++) acc[g][i][j][q] = 0.f;

    issue(0, 0);
    #pragma unroll 1
    for (int kt = 0; kt < 16; kt++) {
        if (kt < 15) { issue((kt + 1) & 1, kt + 1); cpwait<1>(); }
        else         { cpwait<0>(); }
        __syncthreads();

        const uint32_t st = sb + (kt & 1) * STAGE;
        #pragma unroll
        for (int ks = 0; ks < 2; ks++) {
            uint32_t ah[2][4], al[2][4];
            #pragma unroll
            for (int i = 0; i < 2; i++) {
                int rowA = warp_m * 32 + i * 16 + (lane & 15);
                uint32_t off = rowA * A_ST + ks * 32 + (lane >> 4) * 16;
                ldsm_x4(ah[i], st + off);
                ldsm_x4(al[i], st + A_TERM + off);
            }
            #pragma unroll
            for (int g = 0; g < 2; g++) {
                const uint32_t browb = st + B_OFF + g * B_GRP
                    + (ks * 16 + (lane & 15)) * B_ROW + warp_n * 112
                    + (lane >> 4) * 16;

                uint32_t bb[7][2];                    // reused for bh then bl
                #pragma unroll
                for (int jp = 0; jp < 3; jp++) {
                    uint32_t tmp[4];
                    ldsm_x4t(tmp, browb + (2 * jp) * 16);
                    bb[2*jp][0] = tmp[0]; bb[2*jp][1] = tmp[1];
                    bb[2*jp+1][0] = tmp[2]; bb[2*jp+1][1] = tmp[3];
                }
                ldsm_x2t(bb[6], browb + 6 * 16);

                #pragma unroll
                for (int j = 0; j < 7; j++)
                    #pragma unroll
                    for (int i = 0; i < 2; i++)
                        mma16816(acc[g][i][j], ah[i], bb[j]);
                #pragma unroll
                for (int j = 0; j < 7; j++)
                    #pragma unroll
                    for (int i = 0; i < 2; i++)
                        mma16816(acc[g][i][j], al[i], bb[j]);

                #pragma unroll
                for (int jp = 0; jp < 3; jp++) {      // bl into same regs
                    uint32_t tmp[4];
                    ldsm_x4t(tmp, browb + B_TERM + (2 * jp) * 16);
                    bb[2*jp][0] = tmp[0]; bb[2*jp][1] = tmp[1];
                    bb[2*jp+1][0] = tmp[2]; bb[2*jp+1][1] = tmp[3];
                }
                ldsm_x2t(bb[6], browb + B_TERM + 6 * 16);
                #pragma unroll
                for (int j = 0; j < 7; j++)
                    #pragma unroll
                    for (int i = 0; i < 2; i++)
                        mma16816(acc[g][i][j], ah[i], bb[j]);
            }
        }
        __syncthreads();
    }

    // epilogue: both bc groups
    const int gr = lane >> 2, gc = (lane & 3) * 2;
    #pragma unroll
    for (int g = 0; g < 2; g++) {
        const size_t base = (size_t)(bc0 + g) * VL_;
        #pragma unroll
        for (int i = 0; i < 2; i++) {
            #pragma unroll
            for (int j = 0; j < 7; j++) {
                #pragma unroll
                for (int h = 0; h < 2; h++) {
                    int wrow = w0 + warp_m * 32 + i * 16 + gr + h * 8;
                    int lcol = warp_n * 56 + j * 8 + gc;
                    size_t off = base + (size_t)wrow * L_ + lcol;
                    float2 xv = *(const float2*)(xg + off);
                    float o0 = ALPHA * xv.x + OMA * acc[g][i][j][2*h + 0];
                    float o1 = ALPHA * xv.y + OMA * acc[g][i][j][2*h + 1];
                    __nv_bfloat16 b0 = __float2bfloat16_rn(o0);
                    __nv_bfloat16 b1 = __float2bfloat16_rn(o1);
                    *(__nv_bfloat162*)(dhi + off) = __halves2bfloat162(b0, b1);
                    *(__nv_bfloat162*)(dlo + off) = __halves2bfloat162(
                        __float2bfloat16_rn(o0 - __bfloat162float(b0)),
                        __float2bfloat16_rn(o1 - __bfloat162float(b1)));
                }
            }
        }
    }
}

// ---------------- tensor-core channel mix ----------------
#define MROW 272      // padded row stride bytes (128 bf16 = 256B + 16 pad)
#define MTERM 8704    // 32*272
#define WBYTES 17408  // 2 terms of W
#define MSTAGE 17408  // 2 terms of B
#define MIX_SMEM (WBYTES + 2*MSTAGE)   // 52224

__global__ __launch_bounds__(128) void mix_mma(const float* __restrict__ Wg,
                                               const float* __restrict__ bias,
                                               float* __restrict__ out) {
    extern __shared__ char smem[];
    uint32_t sb = (uint32_t)__cvta_generic_to_shared(smem);
    const int t = threadIdx.x;
    const int warp = t >> 5, lane = t & 31;
    const int n0 = blockIdx.x * 128;       // position within (v,l) plane
    const int b = blockIdx.y;
    const size_t boff = (size_t)b * CVL_;

    #pragma unroll
    for (int i = 0; i < 32; i++) {
        int idx = i * 128 + t;             // 4096 total
        int o = idx >> 7, ch = idx & 127;
        float w = Wg[idx];
        __nv_bfloat16 hi = __float2bfloat16_rn(w);
        __nv_bfloat16 lo = __float2bfloat16_rn(w - __bfloat162float(hi));
        *(__nv_bfloat16*)(smem + o * MROW + ch * 2) = hi;
        *(__nv_bfloat16*)(smem + MTERM + o * MROW + ch * 2) = lo;
    }

    const __nv_bfloat16* hitbl[4] = { g_xhi + boff, g_hhi + boff,
                                      g_hhi + NELEM + boff, g_hhi + 2*NELEM + boff };
    const __nv_bfloat16* lotbl[4] = { g_xlo + boff, g_hlo + boff,
                                      g_hlo + NELEM + boff, g_hlo + 2*NELEM + boff };

    auto issue = [&](int s, int kt) {
        uint32_t st = sb + WBYTES + s * MSTAGE;
        #pragma unroll
        for (int i = 0; i < 8; i++) {                  // 1024 chunks exactly
            int c = i * 128 + t;
            int term = c >> 9, rem = c & 511;
            int row = rem >> 4, cc = rem & 15;
            const __nv_bfloat16* src = (term ? lotbl[kt] : hitbl[kt])
                + (size_t)row * VL_ + n0 + cc * 8;
            cpasync16(st + term * MTERM + row * MROW + cc * 16, src);
        }
        cpcommit();
    };

    float acc[2][4][4];
    #pragma unroll
    for (int i = 0; i < 2; i++)
        #pragma unroll
        for (int j = 0; j < 4; j++)
            #pragma unroll
            for (int q = 0; q < 4; q++) acc[i][j][q] = 0.f;

    issue(0, 0);
    #pragma unroll 1
    for (int kt = 0; kt < 4; kt++) {
        if (kt < 3) { issue((kt + 1) & 1, kt + 1); cpwait<1>(); }
        else        { cpwait<0>(); }
        __syncthreads();
        uint32_t st = sb + WBYTES + (kt & 1) * MSTAGE;
        #pragma unroll
        for (int ks = 0; ks < 2; ks++) {
            int kchunk = kt * 2 + ks;
            uint32_t awh[2][4], awl[2][4];
            #pragma unroll
            for (int i = 0; i < 2; i++) {
                int rowA = i * 16 + (lane & 15);
                uint32_t aoff = rowA * MROW + kchunk * 32 + (lane >> 4) * 16;
                ldsm_x4(awh[i], sb + aoff);
                ldsm_x4(awl[i], sb + MTERM + aoff);
            }
            int rowB = ks * 16 + (lane & 15);
            uint32_t bh[4][2], bl[4][2];
            #pragma unroll
            for (int j = 0; j < 4; j++) {
                uint32_t bo = st + rowB * MROW + warp * 64 + j * 16;
                ldsm_x2t(bh[j], bo);
                ldsm_x2t(bl[j], bo + MTERM);
            }
            #pragma unroll
            for (int j = 0; j < 4; j++)
                #pragma unroll
                for (int i = 0; i < 2; i++)
                    mma16816(acc[i][j], awh[i], bh[j]);
            #pragma unroll
            for (int j = 0; j < 4; j++)
                #pragma unroll
                for (int i = 0; i < 2; i++)
                    mma16816(acc[i][j], awh[i], bl[j]);
            #pragma unroll
            for (int j = 0; j < 4; j++)
                #pragma unroll
                for (int i = 0; i < 2; i++)
                    mma16816(acc[i][j], awl[i], bh[j]);
        }
        __syncthreads();
    }

    const int gr = lane >> 2, gc = (lane & 3) * 2;
    #pragma unroll
    for (int i = 0; i < 2; i++) {
        int o0 = i * 16 + gr;
        float bv0 = __ldg(bias + o0);
        float bv1 = __ldg(bias + o0 + 8);
        #pragma unroll
        for (int j = 0; j < 4; j++) {
            int p = n0 + warp * 32 + j * 8 + gc;
            *(float2*)(out + boff + (size_t)o0 * VL_ + p) =
                make_float2(acc[i][j][0] + bv0, acc[i][j][1] + bv0);
            *(float2*)(out + boff + (size_t)(o0 + 8) * VL_ + p) =
                make_float2(acc[i][j][2] + bv1, acc[i][j][3] + bv1);
        }
    }
}

extern "C" void kernel_launch(void* const* d_in, const int* in_sizes, int n_in,
                              void* d_out, int out_size) {
    (void)in_sizes; (void)n_in; (void)out_size;
    const float* x    = (const float*)d_in[0];
    const float* adj  = (const float*)d_in[1];
    const float* W    = (const float*)d_in[2];
    const float* bias = (const float*)d_in[3];
    float* out = (float*)d_out;

    cudaFuncSetAttribute(prop_mma, cudaFuncAttributeMaxDynamicSharedMemorySize,
                         PROP_SMEM);
    cudaFuncSetAttribute(mix_mma, cudaFuncAttributeMaxDynamicSharedMemorySize,
                         MIX_SMEM);

    rowsum_kernel<<<V_, 128>>>(adj);
    buildP_kernel<<<(V_*V_)/256, 256>>>(adj);
    split_kernel<<<(int)(NELEM/4/256), 256>>>(x);

    dim3 pgrid(V_/64, (B_*C_)/2);    // (8, 256) = 2048 CTAs, 2/SM
    prop_mma<<<pgrid, 192, PROP_SMEM>>>(x, -1, 0);   // h1 = f(x)
    prop_mma<<<pgrid, 192, PROP_SMEM>>>(x,  0, 1);   // h2 = f(h1)
    prop_mma<<<pgrid, 192, PROP_SMEM>>>(x,  1, 2);   // h3 = f(h2)

    mix_mma<<<dim3(VL_/128, B_), 128, MIX_SMEM>>>(W, bias, out);
}

// round 14
// speedup vs baseline: 1.1074x; 1.0746x over previous
#include <cuda_runtime.h>
#include <cuda_bf16.h>
#include <cstdint>

#define B_ 16
#define C_ 32
#define V_ 512
#define L_ 168
#define VL_ (V_*L_)                      // 86016
#define CVL_ (C_*VL_)                    // 2752512
#define NELEM ((size_t)B_*C_*V_*L_)      // 44040192
#define ALPHA 0.05f
#define OMA   0.95f

// ---------------- device scratch ----------------
__device__ float g_d[V_];
__device__ __nv_bfloat16 g_Phi[V_*V_];
__device__ __nv_bfloat16 g_Plo[V_*V_];
__device__ __nv_bfloat16 g_xhi[NELEM];
__device__ __nv_bfloat16 g_xlo[NELEM];
__device__ __nv_bfloat16 g_hhi[3*NELEM];
__device__ __nv_bfloat16 g_hlo[3*NELEM];

// ---------------- PTX helpers ----------------
__device__ __forceinline__ void cpasync16(uint32_t dst, const void* src) {
    asm volatile("cp.async.cg.shared.global [%0],[%1],16;\n" :: "r"(dst), "l"(src));
}
__device__ __forceinline__ void cpcommit() { asm volatile("cp.async.commit_group;\n"); }
template<int N> __device__ __forceinline__ void cpwait() {
    asm volatile("cp.async.wait_group %0;\n" :: "n"(N));
}
__device__ __forceinline__ void ldsm_x4(uint32_t a[4], uint32_t addr) {
    asm volatile("ldmatrix.sync.aligned.m8n8.x4.shared.b16 {%0,%1,%2,%3},[%4];"
        : "=r"(a[0]), "=r"(a[1]), "=r"(a[2]), "=r"(a[3]) : "r"(addr));
}
__device__ __forceinline__ void ldsm_x4t(uint32_t a[4], uint32_t addr) {
    asm volatile("ldmatrix.sync.aligned.m8n8.x4.trans.shared.b16 {%0,%1,%2,%3},[%4];"
        : "=r"(a[0]), "=r"(a[1]), "=r"(a[2]), "=r"(a[3]) : "r"(addr));
}
__device__ __forceinline__ void ldsm_x2t(uint32_t b[2], uint32_t addr) {
    asm volatile("ldmatrix.sync.aligned.m8n8.x2.trans.shared.b16 {%0,%1},[%2];"
        : "=r"(b[0]), "=r"(b[1]) : "r"(addr));
}
__device__ __forceinline__ void mma16816(float c[4], const uint32_t a[4], const uint32_t b[2]) {
    asm volatile("mma.sync.aligned.m16n8k16.row.col.f32.bf16.bf16.f32 "
        "{%0,%1,%2,%3},{%4,%5,%6,%7},{%8,%9},{%0,%1,%2,%3};"
        : "+f"(c[0]), "+f"(c[1]), "+f"(c[2]), "+f"(c[3])
        : "r"(a[0]), "r"(a[1]), "r"(a[2]), "r"(a[3]), "r"(b[0]), "r"(b[1]));
}

// ---------------- adjacency prep ----------------
__global__ void rowsum_kernel(const float* __restrict__ adj) {
    int v = blockIdx.x;
    float s = 0.f;
    for (int w = threadIdx.x; w < V_; w += blockDim.x) s += adj[v*V_ + w];
    __shared__ float sh[128];
    sh[threadIdx.x] = s;
    __syncthreads();
    for (int off = 64; off > 0; off >>= 1) {
        if (threadIdx.x < off) sh[threadIdx.x] += sh[threadIdx.x + off];
        __syncthreads();
    }
    if (threadIdx.x == 0) g_d[v] = sh[0] + 1.0f;
}

__global__ void buildP_kernel(const float* __restrict__ adj) {
    int idx = blockIdx.x * blockDim.x + threadIdx.x;   // idx = w*512 + v
    int w = idx >> 9, v = idx & 511;
    float a = adj[v*V_ + w] + (v == w ? 1.f : 0.f);
    float p = a / g_d[v];
    __nv_bfloat16 hi = __float2bfloat16_rn(p);
    g_Phi[idx] = hi;
    g_Plo[idx] = __float2bfloat16_rn(p - __bfloat162float(hi));
}

__global__ void split_kernel(const float* __restrict__ x) {
    size_t i = ((size_t)blockIdx.x * 256 + threadIdx.x) * 4;
    float4 v = *(const float4*)(x + i);
    __nv_bfloat16 h0 = __float2bfloat16_rn(v.x), h1 = __float2bfloat16_rn(v.y);
    __nv_bfloat16 h2 = __float2bfloat16_rn(v.z), h3 = __float2bfloat16_rn(v.w);
    *(__nv_bfloat162*)(g_xhi + i)     = __halves2bfloat162(h0, h1);
    *(__nv_bfloat162*)(g_xhi + i + 2) = __halves2bfloat162(h2, h3);
    *(__nv_bfloat162*)(g_xlo + i)     = __halves2bfloat162(
        __float2bfloat16_rn(v.x - __bfloat162float(h0)),
        __float2bfloat16_rn(v.y - __bfloat162float(h1)));
    *(__nv_bfloat162*)(g_xlo + i + 2) = __halves2bfloat162(
        __float2bfloat16_rn(v.z - __bfloat162float(h2)),
        __float2bfloat16_rn(v.w - __bfloat162float(h3)));
}

// ---------------- tensor-core propagation (R9 configuration) ----------------
// Tile BM=64 x BN=168, BK=32; 192 threads = 6 warps (2m x 3n), warp 32x56.
// 2 CTAs/SM; each CTA does 2 consecutive bc, continuous 3-stage cp.async ring.
#define A_ST   80
#define A_TERM 5120    // 64*80
#define B_OFF  10240   // 2*A_TERM
#define B_ROW  336     // 168 bf16
#define B_TERM 10752   // 32*336
#define STAGE  31744   // B_OFF + 2*B_TERM
#define NSTG   3
#define PROP_SMEM (NSTG*STAGE)   // 95232

__global__ __launch_bounds__(192, 2) void prop_mma(const float* __restrict__ xg,
                                                   int src_sel, int dst_sel) {
    extern __shared__ char smem[];
    uint32_t sb = (uint32_t)__cvta_generic_to_shared(smem);
    const int t = threadIdx.x;
    const int warp = t >> 5, lane = t & 31;
    const int warp_m = warp & 1, warp_n = warp >> 1;     // 2 x 3
    const int w0 = blockIdx.x * 64;
    const int bc0 = blockIdx.y * 2;

    const __nv_bfloat16* __restrict__ shi =
        (src_sel < 0) ? g_xhi : (g_hhi + (size_t)src_sel * NELEM);
    const __nv_bfloat16* __restrict__ slo =
        (src_sel < 0) ? g_xlo : (g_hlo + (size_t)src_sel * NELEM);
    __nv_bfloat16* __restrict__ dhi = g_hhi + (size_t)dst_sel * NELEM;
    __nv_bfloat16* __restrict__ dlo = g_hlo + (size_t)dst_sel * NELEM;

    // one stage = one k-tile of one bc; kk = g*16 + kt
    auto issue = [&](int slot, int kk) {
        const int g = kk >> 4, kt = kk & 15;
        const size_t base = (size_t)(bc0 + g) * VL_;
        const uint32_t st = sb + slot * STAGE;
        #pragma unroll
        for (int i = 0; i < 3; i++) {                 // A: 512 16B chunks
            int c = i * 192 + t;
            if (c < 512) {
                int term = c >> 8, rem = c & 255;
                int row = rem >> 2, q = rem & 3;
                const __nv_bfloat16* src = (term ? g_Plo : g_Phi)
                    + (size_t)(w0 + row) * V_ + kt * 32 + q * 8;
                cpasync16(st + term * A_TERM + row * A_ST + q * 16, src);
            }
        }
        #pragma unroll
        for (int i = 0; i < 7; i++) {                 // B: 1344 16B chunks
            int c = i * 192 + t;
            if (c < 1344) {
                int term = c / 672, rem = c - term * 672;
                int row = rem / 21, cc = rem - row * 21;
                const __nv_bfloat16* src = (term ? slo : shi) + base
                    + (size_t)(kt * 32 + row) * L_ + cc * 8;
                cpasync16(st + B_OFF + term * B_TERM + row * B_ROW + cc * 16, src);
            }
        }
        cpcommit();
    };

    float acc[2][7][4];
    #pragma unroll
    for (int i = 0; i < 2; i++)
        #pragma unroll
        for (int j = 0; j < 7; j++)
            #pragma unroll
            for (int q = 0; q < 4; q++) acc[i][j][q] = 0.f;

    issue(0, 0);
    issue(1, 1);
    for (int kk = 0; kk < 32; kk++) {
        if (kk < 30) { issue((kk + 2) % NSTG, kk + 2); cpwait<2>(); }
        else if (kk == 30) { cpwait<1>(); }
        else { cpwait<0>(); }
        __syncthreads();

        const uint32_t st = sb + (kk % NSTG) * STAGE;
        #pragma unroll
        for (int ks = 0; ks < 2; ks++) {
            const uint32_t browb = st + B_OFF
                + (ks * 16 + (lane & 15)) * B_ROW + warp_n * 112
                + (lane >> 4) * 16;

            uint32_t bh[7][2];
            #pragma unroll
            for (int jp = 0; jp < 3; jp++) {
                uint32_t tmp[4];
                ldsm_x4t(tmp, browb + (2 * jp) * 16);
                bh[2*jp][0] = tmp[0]; bh[2*jp][1] = tmp[1];
                bh[2*jp+1][0] = tmp[2]; bh[2*jp+1][1] = tmp[3];
            }
            ldsm_x2t(bh[6], browb + 6 * 16);

            uint32_t ah[2][4], al[2][4];
            #pragma unroll
            for (int i = 0; i < 2; i++) {
                int rowA = warp_m * 32 + i * 16 + (lane & 15);
                uint32_t off = rowA * A_ST + ks * 32 + (lane >> 4) * 16;
                ldsm_x4(ah[i], st + off);
                ldsm_x4(al[i], st + A_TERM + off);
            }
            #pragma unroll
            for (int j = 0; j < 7; j++)
                #pragma unroll
                for (int i = 0; i < 2; i++) {
                    mma16816(acc[i][j], ah[i], bh[j]);
                    mma16816(acc[i][j], al[i], bh[j]);
                }

            uint32_t bl[7][2];
            #pragma unroll
            for (int jp = 0; jp < 3; jp++) {
                uint32_t tmp[4];
                ldsm_x4t(tmp, browb + B_TERM + (2 * jp) * 16);
                bl[2*jp][0] = tmp[0]; bl[2*jp][1] = tmp[1];
                bl[2*jp+1][0] = tmp[2]; bl[2*jp+1][1] = tmp[3];
            }
            ldsm_x2t(bl[6], browb + B_TERM + 6 * 16);
            #pragma unroll
            for (int j = 0; j < 7; j++)
                #pragma unroll
                for (int i = 0; i < 2; i++)
                    mma16816(acc[i][j], ah[i], bl[j]);
        }

        if ((kk & 15) == 15) {
            const size_t base = (size_t)(bc0 + (kk >> 4)) * VL_;
            const int gr = lane >> 2, gc = (lane & 3) * 2;
            #pragma unroll
            for (int i = 0; i < 2; i++) {
                #pragma unroll
                for (int j = 0; j < 7; j++) {
                    #pragma unroll
                    for (int h = 0; h < 2; h++) {
                        int wrow = w0 + warp_m * 32 + i * 16 + gr + h * 8;
                        int lcol = warp_n * 56 + j * 8 + gc;
                        size_t off = base + (size_t)wrow * L_ + lcol;
                        float2 xv = *(const float2*)(xg + off);
                        float o0 = ALPHA * xv.x + OMA * acc[i][j][2*h + 0];
                        float o1 = ALPHA * xv.y + OMA * acc[i][j][2*h + 1];
                        __nv_bfloat16 b0 = __float2bfloat16_rn(o0);
                        __nv_bfloat16 b1 = __float2bfloat16_rn(o1);
                        *(__nv_bfloat162*)(dhi + off) = __halves2bfloat162(b0, b1);
                        *(__nv_bfloat162*)(dlo + off) = __halves2bfloat162(
                            __float2bfloat16_rn(o0 - __bfloat162float(b0)),
                            __float2bfloat16_rn(o1 - __bfloat162float(b1)));
                        acc[i][j][2*h + 0] = 0.f;
                        acc[i][j][2*h + 1] = 0.f;
                    }
                }
            }
        }
        __syncthreads();
    }
}

// ---------------- tensor-core channel mix (N-tile 256, 8 warps) -------------
#define MROW 272      // W row stride bytes (128 bf16 + 16 pad)
#define MTERM 8704    // 32*272
#define WBYTES 17408  // 2 terms of W
#define FB_ROW 528    // feat row: 256 bf16 = 512B + 16 pad
#define FB_TERM 16896 // 32*528
#define MSTAGE 33792  // 2 terms
#define MIX_SMEM (WBYTES + 2*MSTAGE)   // 84992

__global__ __launch_bounds__(256) void mix_mma(const float* __restrict__ Wg,
                                               const float* __restrict__ bias,
                                               float* __restrict__ out) {
    extern __shared__ char smem[];
    uint32_t sb = (uint32_t)__cvta_generic_to_shared(smem);
    const int t = threadIdx.x;
    const int warp = t >> 5, lane = t & 31;
    const int n0 = blockIdx.x * 256;       // position within (v,l) plane
    const int b = blockIdx.y;
    const size_t boff = (size_t)b * CVL_;

    #pragma unroll
    for (int i = 0; i < 16; i++) {
        int idx = i * 256 + t;             // 4096 total
        int o = idx >> 7, ch = idx & 127;
        float w = Wg[idx];
        __nv_bfloat16 hi = __float2bfloat16_rn(w);
        __nv_bfloat16 lo = __float2bfloat16_rn(w - __bfloat162float(hi));
        *(__nv_bfloat16*)(smem + o * MROW + ch * 2) = hi;
        *(__nv_bfloat16*)(smem + MTERM + o * MROW + ch * 2) = lo;
    }

    const __nv_bfloat16* hitbl[4] = { g_xhi + boff, g_hhi + boff,
                                      g_hhi + NELEM + boff, g_hhi + 2*NELEM + boff };
    const __nv_bfloat16* lotbl[4] = { g_xlo + boff, g_hlo + boff,
                                      g_hlo + NELEM + boff, g_hlo + 2*NELEM + boff };

    auto issue = [&](int s, int kt) {
        uint32_t st = sb + WBYTES + s * MSTAGE;
        #pragma unroll
        for (int i = 0; i < 8; i++) {                  // 2048 chunks exactly
            int c = i * 256 + t;
            int term = c >> 10, rem = c & 1023;
            int row = rem >> 5, cc = rem & 31;         // row = channel-in-slot
            const __nv_bfloat16* src = (term ? lotbl[kt] : hitbl[kt])
                + (size_t)row * VL_ + n0 + cc * 8;
            cpasync16(st + term * FB_TERM + row * FB_ROW + cc * 16, src);
        }
        cpcommit();
    };

    float acc[2][4][4];
    #pragma unroll
    for (int i = 0; i < 2; i++)
        #pragma unroll
        for (int j = 0; j < 4; j++)
            #pragma unroll
            for (int q = 0; q < 4; q++) acc[i][j][q] = 0.f;

    issue(0, 0);
    for (int kt = 0; kt < 4; kt++) {
        if (kt < 3) { issue((kt + 1) & 1, kt + 1); cpwait<1>(); }
        else        { cpwait<0>(); }
        __syncthreads();
        uint32_t st = sb + WBYTES + (kt & 1) * MSTAGE;
        #pragma unroll
        for (int ks = 0; ks < 2; ks++) {
            int kchunk = kt * 2 + ks;
            uint32_t awh[2][4], awl[2][4];
            #pragma unroll
            for (int i = 0; i < 2; i++) {
                int rowA = i * 16 + (lane & 15);
                uint32_t aoff = rowA * MROW + kchunk * 32 + (lane >> 4) * 16;
                ldsm_x4(awh[i], sb + aoff);
                ldsm_x4(awl[i], sb + MTERM + aoff);
            }
            int rowB = ks * 16 + (lane & 15);
            uint32_t bh[4][2], bl[4][2];
            #pragma unroll
            for (int j = 0; j < 4; j++) {
                uint32_t bo = st + rowB * FB_ROW + warp * 64 + j * 16;
                ldsm_x2t(bh[j], bo);
                ldsm_x2t(bl[j], bo + FB_TERM);
            }
            #pragma unroll
            for (int j = 0; j < 4; j++)
                #pragma unroll
                for (int i = 0; i < 2; i++)
                    mma16816(acc[i][j], awh[i], bh[j]);
            #pragma unroll
            for (int j = 0; j < 4; j++)
                #pragma unroll
                for (int i = 0; i < 2; i++)
                    mma16816(acc[i][j], awh[i], bl[j]);
            #pragma unroll
            for (int j = 0; j < 4; j++)
                #pragma unroll
                for (int i = 0; i < 2; i++)
                    mma16816(acc[i][j], awl[i], bh[j]);
        }
        __syncthreads();
    }

    const int gr = lane >> 2, gc = (lane & 3) * 2;
    #pragma unroll
    for (int i = 0; i < 2; i++) {
        int o0 = i * 16 + gr;
        float bv0 = __ldg(bias + o0);
        float bv1 = __ldg(bias + o0 + 8);
        #pragma unroll
        for (int j = 0; j < 4; j++) {
            int p = n0 + warp * 32 + j * 8 + gc;
            *(float2*)(out + boff + (size_t)o0 * VL_ + p) =
                make_float2(acc[i][j][0] + bv0, acc[i][j][1] + bv0);
            *(float2*)(out + boff + (size_t)(o0 + 8) * VL_ + p) =
                make_float2(acc[i][j][2] + bv1, acc[i][j][3] + bv1);
        }
    }
}

extern "C" void kernel_launch(void* const* d_in, const int* in_sizes, int n_in,
                              void* d_out, int out_size) {
    (void)in_sizes; (void)n_in; (void)out_size;
    const float* x    = (const float*)d_in[0];
    const float* adj  = (const float*)d_in[1];
    const float* W    = (const float*)d_in[2];
    const float* bias = (const float*)d_in[3];
    float* out = (float*)d_out;

    cudaFuncSetAttribute(prop_mma, cudaFuncAttributeMaxDynamicSharedMemorySize,
                         PROP_SMEM);
    cudaFuncSetAttribute(mix_mma, cudaFuncAttributeMaxDynamicSharedMemorySize,
                         MIX_SMEM);

    rowsum_kernel<<<V_, 128>>>(adj);
    buildP_kernel<<<(V_*V_)/256, 256>>>(adj);
    split_kernel<<<(int)(NELEM/4/256), 256>>>(x);

    dim3 pgrid(V_/64, (B_*C_)/2);    // (8, 256) = 2048 CTAs, 2/SM
    prop_mma<<<pgrid, 192, PROP_SMEM>>>(x, -1, 0);   // h1 = f(x)
    prop_mma<<<pgrid, 192, PROP_SMEM>>>(x,  0, 1);   // h2 = f(h1)
    prop_mma<<<pgrid, 192, PROP_SMEM>>>(x,  1, 2);   // h3 = f(h2)

    mix_mma<<<dim3(VL_/256, B_), 256, MIX_SMEM>>>(W, bias, out);
}

// round 17
// speedup vs baseline: 1.5204x; 1.3730x over previous
#include <cuda_runtime.h>
#include <cuda_fp16.h>
#include <cstdint>

#define B_ 16
#define C_ 32
#define V_ 512
#define L_ 168
#define VL_ (V_*L_)                      // 86016
#define CVL_ (C_*VL_)                    // 2752512
#define NELEM ((size_t)B_*C_*V_*L_)      // 44040192
#define ALPHA 0.05f
#define OMA   0.95f

// ---------------- device scratch ----------------
__device__ float g_d[V_];
__device__ __half g_Pf[V_*V_];           // P single fp16 (11-bit mantissa)
__device__ __half g_xhi[NELEM];
__device__ __half g_xlo[NELEM];
__device__ __half g_hhi[3*NELEM];
__device__ __half g_hlo[3*NELEM];

// ---------------- PTX helpers ----------------
__device__ __forceinline__ void cpasync16(uint32_t dst, const void* src) {
    asm volatile("cp.async.cg.shared.global [%0],[%1],16;\n" :: "r"(dst), "l"(src));
}
__device__ __forceinline__ void cpcommit() { asm volatile("cp.async.commit_group;\n"); }
template<int N> __device__ __forceinline__ void cpwait() {
    asm volatile("cp.async.wait_group %0;\n" :: "n"(N));
}
__device__ __forceinline__ void ldsm_x4(uint32_t a[4], uint32_t addr) {
    asm volatile("ldmatrix.sync.aligned.m8n8.x4.shared.b16 {%0,%1,%2,%3},[%4];"
        : "=r"(a[0]), "=r"(a[1]), "=r"(a[2]), "=r"(a[3]) : "r"(addr));
}
__device__ __forceinline__ void ldsm_x4t(uint32_t a[4], uint32_t addr) {
    asm volatile("ldmatrix.sync.aligned.m8n8.x4.trans.shared.b16 {%0,%1,%2,%3},[%4];"
        : "=r"(a[0]), "=r"(a[1]), "=r"(a[2]), "=r"(a[3]) : "r"(addr));
}
__device__ __forceinline__ void ldsm_x2t(uint32_t b[2], uint32_t addr) {
    asm volatile("ldmatrix.sync.aligned.m8n8.x2.trans.shared.b16 {%0,%1},[%2];"
        : "=r"(b[0]), "=r"(b[1]) : "r"(addr));
}
__device__ __forceinline__ void mma16816(float c[4], const uint32_t a[4], const uint32_t b[2]) {
    asm volatile("mma.sync.aligned.m16n8k16.row.col.f32.f16.f16.f32 "
        "{%0,%1,%2,%3},{%4,%5,%6,%7},{%8,%9},{%0,%1,%2,%3};"
        : "+f"(c[0]), "+f"(c[1]), "+f"(c[2]), "+f"(c[3])
        : "r"(a[0]), "r"(a[1]), "r"(a[2]), "r"(a[3]), "r"(b[0]), "r"(b[1]));
}

// ---------------- adjacency prep ----------------
__global__ void rowsum_kernel(const float* __restrict__ adj) {
    int v = blockIdx.x;
    float s = 0.f;
    for (int w = threadIdx.x; w < V_; w += blockDim.x) s += adj[v*V_ + w];
    __shared__ float sh[128];
    sh[threadIdx.x] = s;
    __syncthreads();
    for (int off = 64; off > 0; off >>= 1) {
        if (threadIdx.x < off) sh[threadIdx.x] += sh[threadIdx.x + off];
        __syncthreads();
    }
    if (threadIdx.x == 0) g_d[v] = sh[0] + 1.0f;
}

__global__ void buildP_kernel(const float* __restrict__ adj) {
    int idx = blockIdx.x * blockDim.x + threadIdx.x;   // idx = w*512 + v
    int w = idx >> 9, v = idx & 511;
    float a = adj[v*V_ + w] + (v == w ? 1.f : 0.f);
    g_Pf[idx] = __float2half_rn(a / g_d[v]);
}

__global__ void split_kernel(const float* __restrict__ x) {
    size_t i = ((size_t)blockIdx.x * 256 + threadIdx.x) * 4;
    float4 v = *(const float4*)(x + i);
    __half h0 = __float2half_rn(v.x), h1 = __float2half_rn(v.y);
    __half h2 = __float2half_rn(v.z), h3 = __float2half_rn(v.w);
    *(__half2*)(g_xhi + i)     = __halves2half2(h0, h1);
    *(__half2*)(g_xhi + i + 2) = __halves2half2(h2, h3);
    *(__half2*)(g_xlo + i)     = __halves2half2(
        __float2half_rn(v.x - __half2float(h0)),
        __float2half_rn(v.y - __half2float(h1)));
    *(__half2*)(g_xlo + i + 2) = __halves2half2(
        __float2half_rn(v.z - __half2float(h2)),
        __float2half_rn(v.w - __half2float(h3)));
}

// ---------------- tensor-core propagation (fp16, 2-term) --------------------
// Tile BM=64 x BN=168, BK=32; 192 threads = 6 warps (2m x 3n), warp 32x56.
// 2 CTAs/SM; each CTA does 2 consecutive bc, continuous 3-stage cp.async ring.
// D = Pf*Shi + Pf*Slo; out = ALPHA*x + OMA*D -> fp16 hi/lo split.
#define A_ST   80
#define A_SZ   5120    // 64 rows x 80B (single P plane)
#define B_OFF  5120
#define B_ROW  336     // 168 fp16
#define B_TERM 10752   // 32*336
#define STAGE  26624   // B_OFF + 2*B_TERM
#define NSTG   3
#define PROP_SMEM (NSTG*STAGE)   // 79872

__global__ __launch_bounds__(192, 2) void prop_mma(const float* __restrict__ xg,
                                                   int src_sel, int dst_sel) {
    extern __shared__ char smem[];
    uint32_t sb = (uint32_t)__cvta_generic_to_shared(smem);
    const int t = threadIdx.x;
    const int warp = t >> 5, lane = t & 31;
    const int warp_m = warp & 1, warp_n = warp >> 1;     // 2 x 3
    const int w0 = blockIdx.x * 64;
    const int bc0 = blockIdx.y * 2;

    const __half* __restrict__ shi =
        (src_sel < 0) ? g_xhi : (g_hhi + (size_t)src_sel * NELEM);
    const __half* __restrict__ slo =
        (src_sel < 0) ? g_xlo : (g_hlo + (size_t)src_sel * NELEM);
    __half* __restrict__ dhi = g_hhi + (size_t)dst_sel * NELEM;
    __half* __restrict__ dlo = g_hlo + (size_t)dst_sel * NELEM;

    // one stage = one k-tile of one bc; kk = g*16 + kt
    auto issue = [&](int slot, int kk) {
        const int g = kk >> 4, kt = kk & 15;
        const size_t base = (size_t)(bc0 + g) * VL_;
        const uint32_t st = sb + slot * STAGE;
        #pragma unroll
        for (int i = 0; i < 2; i++) {                 // A: 256 16B chunks
            int c = i * 192 + t;
            if (c < 256) {
                int row = c >> 2, q = c & 3;
                const __half* src = g_Pf
                    + (size_t)(w0 + row) * V_ + kt * 32 + q * 8;
                cpasync16(st + row * A_ST + q * 16, src);
            }
        }
        #pragma unroll
        for (int i = 0; i < 7; i++) {                 // B: 1344 16B chunks
            int c = i * 192 + t;
            if (c < 1344) {
                int term = c / 672, rem = c - term * 672;
                int row = rem / 21, cc = rem - row * 21;
                const __half* src = (term ? slo : shi) + base
                    + (size_t)(kt * 32 + row) * L_ + cc * 8;
                cpasync16(st + B_OFF + term * B_TERM + row * B_ROW + cc * 16, src);
            }
        }
        cpcommit();
    };

    float acc[2][7][4];
    #pragma unroll
    for (int i = 0; i < 2; i++)
        #pragma unroll
        for (int j = 0; j < 7; j++)
            #pragma unroll
            for (int q = 0; q < 4; q++) acc[i][j][q] = 0.f;

    issue(0, 0);
    issue(1, 1);
    for (int kk = 0; kk < 32; kk++) {
        if (kk < 30) { issue((kk + 2) % NSTG, kk + 2); cpwait<2>(); }
        else if (kk == 30) { cpwait<1>(); }
        else { cpwait<0>(); }
        __syncthreads();

        const uint32_t st = sb + (kk % NSTG) * STAGE;
        #pragma unroll
        for (int ks = 0; ks < 2; ks++) {
            const uint32_t browb = st + B_OFF
                + (ks * 16 + (lane & 15)) * B_ROW + warp_n * 112
                + (lane >> 4) * 16;

            uint32_t bh[7][2];
            #pragma unroll
            for (int jp = 0; jp < 3; jp++) {
                uint32_t tmp[4];
                ldsm_x4t(tmp, browb + (2 * jp) * 16);
                bh[2*jp][0] = tmp[0]; bh[2*jp][1] = tmp[1];
                bh[2*jp+1][0] = tmp[2]; bh[2*jp+1][1] = tmp[3];
            }
            ldsm_x2t(bh[6], browb + 6 * 16);

            uint32_t ah[2][4];
            #pragma unroll
            for (int i = 0; i < 2; i++) {
                int rowA = warp_m * 32 + i * 16 + (lane & 15);
                ldsm_x4(ah[i], st + rowA * A_ST + ks * 32 + (lane >> 4) * 16);
            }
            #pragma unroll
            for (int j = 0; j < 7; j++)
                #pragma unroll
                for (int i = 0; i < 2; i++)
                    mma16816(acc[i][j], ah[i], bh[j]);

            uint32_t bl[7][2];
            #pragma unroll
            for (int jp = 0; jp < 3; jp++) {
                uint32_t tmp[4];
                ldsm_x4t(tmp, browb + B_TERM + (2 * jp) * 16);
                bl[2*jp][0] = tmp[0]; bl[2*jp][1] = tmp[1];
                bl[2*jp+1][0] = tmp[2]; bl[2*jp+1][1] = tmp[3];
            }
            ldsm_x2t(bl[6], browb + B_TERM + 6 * 16);
            #pragma unroll
            for (int j = 0; j < 7; j++)
                #pragma unroll
                for (int i = 0; i < 2; i++)
                    mma16816(acc[i][j], ah[i], bl[j]);
        }

        if ((kk & 15) == 15) {
            // epilogue for bc = bc0 + (kk>>4); next-bc loads already in flight
            const size_t base = (size_t)(bc0 + (kk >> 4)) * VL_;
            const int gr = lane >> 2, gc = (lane & 3) * 2;
            #pragma unroll
            for (int i = 0; i < 2; i++) {
                #pragma unroll
                for (int j = 0; j < 7; j++) {
                    #pragma unroll
                    for (int h = 0; h < 2; h++) {
                        int wrow = w0 + warp_m * 32 + i * 16 + gr + h * 8;
                        int lcol = warp_n * 56 + j * 8 + gc;
                        size_t off = base + (size_t)wrow * L_ + lcol;
                        float2 xv = *(const float2*)(xg + off);
                        float o0 = ALPHA * xv.x + OMA * acc[i][j][2*h + 0];
                        float o1 = ALPHA * xv.y + OMA * acc[i][j][2*h + 1];
                        __half b0 = __float2half_rn(o0);
                        __half b1 = __float2half_rn(o1);
                        *(__half2*)(dhi + off) = __halves2half2(b0, b1);
                        *(__half2*)(dlo + off) = __halves2half2(
                            __float2half_rn(o0 - __half2float(b0)),
                            __float2half_rn(o1 - __half2float(b1)));
                        acc[i][j][2*h + 0] = 0.f;
                        acc[i][j][2*h + 1] = 0.f;
                    }
                }
            }
        }
        __syncthreads();
    }
}

// ---------------- tensor-core channel mix (single-term fp16) ----------------
#define MROW 272      // row stride bytes (128 fp16 = 256B + 16 pad)
#define WBYTES 8704   // W single term (32*272)
#define MSTAGE 8704   // feats hi only per stage
#define MIX_SMEM (WBYTES + 2*MSTAGE)   // 26112

__global__ __launch_bounds__(128) void mix_mma(const float* __restrict__ Wg,
                                               const float* __restrict__ bias,
                                               float* __restrict__ out) {
    extern __shared__ char smem[];
    uint32_t sb = (uint32_t)__cvta_generic_to_shared(smem);
    const int t = threadIdx.x;
    const int warp = t >> 5, lane = t & 31;
    const int n0 = blockIdx.x * 128;       // position within (v,l) plane
    const int b = blockIdx.y;
    const size_t boff = (size_t)b * CVL_;

    #pragma unroll
    for (int i = 0; i < 32; i++) {
        int idx = i * 128 + t;             // 4096 total
        int o = idx >> 7, ch = idx & 127;
        *(__half*)(smem + o * MROW + ch * 2) = __float2half_rn(Wg[idx]);
    }

    const __half* hitbl[4] = { g_xhi + boff, g_hhi + boff,
                               g_hhi + NELEM + boff, g_hhi + 2*NELEM + boff };

    auto issue = [&](int s, int kt) {
        uint32_t st = sb + WBYTES + s * MSTAGE;
        #pragma unroll
        for (int i = 0; i < 4; i++) {                  // 512 chunks exactly
            int c = i * 128 + t;
            int row = c >> 4, cc = c & 15;             // row = channel-in-slot
            const __half* src = hitbl[kt] + (size_t)row * VL_ + n0 + cc * 8;
            cpasync16(st + row * MROW + cc * 16, src);
        }
        cpcommit();
    };

    float acc[2][4][4];
    #pragma unroll
    for (int i = 0; i < 2; i++)
        #pragma unroll
        for (int j = 0; j < 4; j++)
            #pragma unroll
            for (int q = 0; q < 4; q++) acc[i][j][q] = 0.f;

    issue(0, 0);
    for (int kt = 0; kt < 4; kt++) {
        if (kt < 3) { issue((kt + 1) & 1, kt + 1); cpwait<1>(); }
        else        { cpwait<0>(); }
        __syncthreads();
        uint32_t st = sb + WBYTES + (kt & 1) * MSTAGE;
        #pragma unroll
        for (int ks = 0; ks < 2; ks++) {
            int kchunk = kt * 2 + ks;
            uint32_t awh[2][4];
            #pragma unroll
            for (int i = 0; i < 2; i++) {
                int rowA = i * 16 + (lane & 15);
                ldsm_x4(awh[i], sb + rowA * MROW + kchunk * 32 + (lane >> 4) * 16);
            }
            int rowB = ks * 16 + (lane & 15);
            uint32_t bh[4][2];
            #pragma unroll
            for (int j = 0; j < 4; j++)
                ldsm_x2t(bh[j], st + rowB * MROW + warp * 64 + j * 16);
            #pragma unroll
            for (int j = 0; j < 4; j++)
                #pragma unroll
                for (int i = 0; i < 2; i++)
                    mma16816(acc[i][j], awh[i], bh[j]);
        }
        __syncthreads();
    }

    const int gr = lane >> 2, gc = (lane & 3) * 2;
    #pragma unroll
    for (int i = 0; i < 2; i++) {
        int o0 = i * 16 + gr;
        float bv0 = __ldg(bias + o0);
        float bv1 = __ldg(bias + o0 + 8);
        #pragma unroll
        for (int j = 0; j < 4; j++) {
            int p = n0 + warp * 32 + j * 8 + gc;
            *(float2*)(out + boff + (size_t)o0 * VL_ + p) =
                make_float2(acc[i][j][0] + bv0, acc[i][j][1] + bv0);
            *(float2*)(out + boff + (size_t)(o0 + 8) * VL_ + p) =
                make_float2(acc[i][j][2] + bv1, acc[i][j][3] + bv1);
        }
    }
}

extern "C" void kernel_launch(void* const* d_in, const int* in_sizes, int n_in,
                              void* d_out, int out_size) {
    (void)in_sizes; (void)n_in; (void)out_size;
    const float* x    = (const float*)d_in[0];
    const float* adj  = (const float*)d_in[1];
    const float* W    = (const float*)d_in[2];
    const float* bias = (const float*)d_in[3];
    float* out = (float*)d_out;

    cudaFuncSetAttribute(prop_mma, cudaFuncAttributeMaxDynamicSharedMemorySize,
                         PROP_SMEM);
    cudaFuncSetAttribute(mix_mma, cudaFuncAttributeMaxDynamicSharedMemorySize,
                         MIX_SMEM);

    rowsum_kernel<<<V_, 128>>>(adj);
    buildP_kernel<<<(V_*V_)/256, 256>>>(adj);
    split_kernel<<<(int)(NELEM/4/256), 256>>>(x);

    dim3 pgrid(V_/64, (B_*C_)/2);    // (8, 256) = 2048 CTAs, 2/SM
    prop_mma<<<pgrid, 192, PROP_SMEM>>>(x, -1, 0);   // h1 = f(x)
    prop_mma<<<pgrid, 192, PROP_SMEM>>>(x,  0, 1);   // h2 = f(h1)
    prop_mma<<<pgrid, 192, PROP_SMEM>>>(x,  1, 2);   // h3 = f(h2)

    mix_mma<<<dim3(VL_/128, B_), 128, MIX_SMEM>>>(W, bias, out);
}